// round 1
// baseline (speedup 1.0000x reference)
#include <cuda_runtime.h>
#include <cuda_bf16.h>

#define IMG 256
#define TILE 32
#define HALO 3
#define SW (TILE + 2 * HALO)      // 38
#define SPITCH 40                 // padded pitch to keep banks clean

__global__ __launch_bounds__(256, 3)
void AdaptiveGaussianFilter_66675072303489_kernel(
    const float* __restrict__ x,
    const float* __restrict__ sigma,
    float* __restrict__ out)
{
    __shared__ float sm[SW][SPITCH];

    const int ch = blockIdx.z;               // 0..47 (batch*channel)
    const int x0 = blockIdx.x * TILE;
    const int y0 = blockIdx.y * TILE;

    const float* xc = x     + (size_t)ch * IMG * IMG;
    const float* sc = sigma + (size_t)ch * IMG * IMG;
    float*       oc = out   + (size_t)ch * IMG * IMG;

    const int tid = threadIdx.y * 32 + threadIdx.x;

    // Cooperative load of 38x38 halo tile with reflect padding
    #pragma unroll
    for (int i = tid; i < SW * SW; i += 256) {
        int sy = i / SW;
        int sx = i - sy * SW;
        int gy = y0 + sy - HALO;
        int gx = x0 + sx - HALO;
        gy = (gy < 0) ? -gy : ((gy > IMG - 1) ? 2 * (IMG - 1) - gy : gy);
        gx = (gx < 0) ? -gx : ((gx > IMG - 1) ? 2 * (IMG - 1) - gx : gx);
        sm[sy][sx] = xc[gy * IMG + gx];
    }
    __syncthreads();

    const int lx  = threadIdx.x;              // 0..31 output column in tile
    const int ly0 = threadIdx.y * 4;          // 4 consecutive output rows per thread

    // Rolling 7x7 register window over shared memory
    float w[7][7];
    #pragma unroll
    for (int i = 0; i < 7; i++)
        #pragma unroll
        for (int j = 0; j < 7; j++)
            w[i][j] = sm[ly0 + i][lx + j];

    #pragma unroll
    for (int k = 0; k < 4; k++) {
        const int ly = ly0 + k;
        const int gy = y0 + ly;
        const int gx = x0 + lx;

        // Separable weights from one exp: t = exp(-sigma^2/2)
        float s  = sc[gy * IMG + gx];
        float s2 = s * s;
        float t  = __expf(-0.5f * s2);
        float t2 = t * t;
        float t4 = t2 * t2;
        float t9 = t4 * t4 * t;
        float S  = fmaf(2.0f, t + t4 + t9, 1.0f);
        float inv = __fdividef(1.0f, S * S);

        float acc = 0.0f;
        #pragma unroll
        for (int r = 0; r < 7; r++) {
            const int slot = (k + r) % 7;     // logical row r -> register slot
            float h = fmaf(t,  w[slot][2] + w[slot][4],
                     fmaf(t4, w[slot][1] + w[slot][5],
                     fmaf(t9, w[slot][0] + w[slot][6], w[slot][3])));
            float ur = (r == 3) ? 1.0f
                     : ((r == 2 || r == 4) ? t
                     : ((r == 1 || r == 5) ? t4 : t9));
            acc = fmaf(ur, h, acc);
        }

        oc[gy * IMG + gx] = acc * inv;

        // Slide window: bring in shared row ly0 + 7 + k into retired slot
        if (k < 3) {
            #pragma unroll
            for (int j = 0; j < 7; j++)
                w[k % 7][j] = sm[ly0 + 7 + k][lx + j];
        }
    }
}

extern "C" void kernel_launch(void* const* d_in, const int* in_sizes, int n_in,
                              void* d_out, int out_size)
{
    const float* x     = (const float*)d_in[0];
    const float* sigma = (const float*)d_in[1];
    float*       out   = (float*)d_out;

    dim3 block(32, 8, 1);
    dim3 grid(IMG / TILE, IMG / TILE, 16 * 3);   // 8 x 8 x 48
    AdaptiveGaussianFilter_66675072303489_kernel<<<grid, block>>>(x, sigma, out);
}